// round 9
// baseline (speedup 1.0000x reference)
#include <cuda_runtime.h>
#include <math.h>
#include <stdint.h>

// Scratch: Q1 ping-pong in both layouts. [B,S,S], B=4,S=160 -> 102400
#define MAXQ 102400
#define MAXR 1024                  // max B*S rows
__device__ __align__(16) float g_q1 [2][MAXQ];   // Q1[b,m,h]
__device__ __align__(16) float g_q1T[2][MAXQ];   // Q1[b,h,m]
__device__ int   g_excl[MAXQ];     // per (b,h): excluded t list (mask[b,t,h]==0 || t==h)
__device__ int   g_ecnt[MAXR];     // per (b,h): list length

__device__ __forceinline__ uint32_t smem_u32(const void* p) {
    uint32_t a;
    asm("{ .reg .u64 t; cvta.to.shared.u64 t, %1; cvt.u32.u64 %0, t; }" : "=r"(a) : "l"(p));
    return a;
}

// Pre-pass: build per-(b,h) exclusion list.
__global__ void excl_build_kernel(const int* __restrict__ mask, int S)
{
    __shared__ int cnt;
    int t = threadIdx.x;
    int h = blockIdx.x % S;
    int b = blockIdx.x / S;
    int row = b * S + h;
    if (t == 0) cnt = 0;
    __syncthreads();
    if (t < S) {
        bool ex = (mask[(b * S + t) * S + h] == 0) || (t == h);
        if (ex) {
            int slot = atomicAdd(&cnt, 1);
            g_excl[row * S + slot] = t;
        }
    }
    __syncthreads();
    if (t == 0) g_ecnt[row] = cnt;
}

// MODE 0: iter 1, Q1 == 0.5. MODE 1: middle iter. MODE 2: final -> output.
// 128 threads, 16 h-rows per block, scores staged via cp.async.bulk into smem.
template<int MODE>
__global__ void __launch_bounds__(128, 7)
mfvi_kernel(const float* __restrict__ se,
            const float* __restrict__ ss,
            const float* __restrict__ sc,
            const float* __restrict__ sg,
            const int* __restrict__ mask,
            float* __restrict__ out,
            int S, int parity)
{
    const int ROWS = 16;
    int ntile = (S + ROWS - 1) / ROWS;
    int blk = blockIdx.x;
    int htile = blk % ntile;
    int m     = (blk / ntile) % S;
    int b     = blk / (ntile * S);
    int warp = threadIdx.x >> 5;           // 0..3
    int lane = threadIdx.x & 31;
    int g    = lane >> 3;                  // 8-lane group -> row
    int li   = lane & 7;
    int rt   = warp * 4 + g;               // row within tile 0..15
    int h0b  = htile * ROWS;
    int h    = h0b + rt;
    int rows = (S - h0b < ROWS) ? (S - h0b) : ROWS;

    extern __shared__ float smbuf[];
    float* sm_row = smbuf;                 // Q1[b,m,t]   [S]
    float* sm_col = smbuf + S;             // Q1[b,t,m]   [S]
    unsigned long long* bar = (unsigned long long*)(smbuf + 2 * S);
    float* d_ss = smbuf + 2 * S + 32;      // 128B-aligned data region
    float* d_sc = d_ss + ROWS * S;
    float* d_sg = d_sc + ROWS * S;

    uint32_t bar_a = smem_u32(bar);
    int tid = threadIdx.x;

    if (tid == 0) {
        asm volatile("mbarrier.init.shared.b64 [%0], %1;" :: "r"(bar_a), "r"(1) : "memory");
    }
    __syncthreads();

    const long sbase0 = (((long)(b * S + m)) * S + h0b) * S;  // first staged score element
    int nbytes = rows * S * 4;

    if (tid == 0) {
        asm volatile("mbarrier.arrive.expect_tx.shared.b64 _, [%0], %1;"
                     :: "r"(bar_a), "r"(3 * nbytes) : "memory");
        asm volatile("cp.async.bulk.shared::cluster.global.mbarrier::complete_tx::bytes [%0], [%1], %2, [%3];"
                     :: "r"(smem_u32(d_ss)), "l"(ss + sbase0), "r"(nbytes), "r"(bar_a) : "memory");
        asm volatile("cp.async.bulk.shared::cluster.global.mbarrier::complete_tx::bytes [%0], [%1], %2, [%3];"
                     :: "r"(smem_u32(d_sc)), "l"(sc + sbase0), "r"(nbytes), "r"(bar_a) : "memory");
        asm volatile("cp.async.bulk.shared::cluster.global.mbarrier::complete_tx::bytes [%0], [%1], %2, [%3];"
                     :: "r"(smem_u32(d_sg)), "l"(sg + sbase0), "r"(nbytes), "r"(bar_a) : "memory");
    }

    const float* __restrict__ q1_in  = g_q1 [parity & 1];
    const float* __restrict__ q1T_in = g_q1T[parity & 1];

    if (MODE != 0) {   // stage q1 row/col while the bulk copies fly
        int nv = S >> 2;
        const float4* r4 = (const float4*)(q1_in  + (b * S + m) * S);
        const float4* c4 = (const float4*)(q1T_in + (b * S + m) * S);
        for (int i = tid; i < 2 * nv; i += blockDim.x) {
            if (i < nv) ((float4*)sm_row)[i] = r4[i];
            else        ((float4*)sm_col)[i - nv] = c4[i - nv];
        }
    }
    __syncthreads();

    // wait for bulk copies (parity 0, acquire)
    {
        uint32_t done;
        asm volatile(
            "{\n\t.reg .pred P;\n\t"
            "mbarrier.try_wait.parity.acquire.cta.shared::cta.b64 P, [%1], %2;\n\t"
            "selp.b32 %0, 1, 0, P;\n\t}"
            : "=r"(done) : "r"(bar_a), "r"(0) : "memory");
        if (!done) {
            asm volatile(
                "{\n\t.reg .pred P1;\n\t"
                "W%=:\n\t"
                "mbarrier.try_wait.parity.acquire.cta.shared::cta.b64 P1, [%0], %1, 0x989680;\n\t"
                "@P1 bra D%=;\n\t"
                "bra W%=;\n\t"
                "D%=:\n\t}"
                :: "r"(bar_a), "r"(0) : "memory");
        }
    }

    int FV = S >> 2;
    const long hbase = ((long)(b * S + h)) * S;
    const float4* pss = (const float4*)(d_ss + rt * S);
    const float4* psc = (const float4*)(d_sc + rt * S);
    const float4* psg = (const float4*)(d_sg + rt * S);
    const float4* pqa = (const float4*)(q1T_in + hbase);
    const float4* srow = (const float4*)sm_row;
    const float4* scol = (const float4*)sm_col;

    // Unmasked full sum over t; exclusions subtracted afterward.
    float acc = 0.f;
    if (rt < rows) {
        #pragma unroll 5
        for (int v = li; v < FV; v += 8) {
            float4 vss = pss[v];
            float4 vsc = psc[v];
            float4 vsg = psg[v];
            if (MODE == 0) {
                #pragma unroll
                for (int j = 0; j < 4; j++)
                    acc += (&vss.x)[j] + (&vsc.x)[j] + (&vsg.x)[j];
            } else {
                float4 vqa = pqa[v];
                float4 vr  = srow[v];
                float4 vc  = scol[v];
                #pragma unroll
                for (int j = 0; j < 4; j++) {
                    acc += (&vss.x)[j] * (&vqa.x)[j];
                    acc += (&vsc.x)[j] * (&vr.x)[j];
                    acc += (&vsg.x)[j] * (&vc.x)[j];
                }
            }
        }
    }

    // reduce within the 8-lane group
    acc += __shfl_down_sync(0xffffffffu, acc, 4, 8);
    acc += __shfl_down_sync(0xffffffffu, acc, 2, 8);
    acc += __shfl_down_sync(0xffffffffu, acc, 1, 8);

    if (li == 0 && rt < rows) {
        const float* ss_r = d_ss + rt * S;
        const float* sc_r = d_sc + rt * S;
        const float* sg_r = d_sg + rt * S;
        int idx = (b * S + m) * S + h;
        float f = 0.f;
        if (mask[idx] != 0) {
            if (MODE == 0) acc *= 0.5f;
            int row = b * S + h;
            int cnt = g_ecnt[row];
            for (int i = 0; i < cnt; i++) {
                int t = g_excl[row * S + i];
                if (MODE == 0)
                    acc -= 0.5f * (ss_r[t] + sc_r[t] + sg_r[t]);
                else
                    acc -= ss_r[t] * q1T_in[hbase + t]
                         + sc_r[t] * sm_row[t]
                         + sg_r[t] * sm_col[t];
            }
            if (m != h) {   // t == m exclusion (not in list when mask[b,m,h]!=0)
                if (MODE == 0)
                    acc -= 0.5f * (ss_r[m] + sc_r[m] + sg_r[m]);
                else
                    acc -= ss_r[m] * q1T_in[hbase + m]
                         + sc_r[m] * sm_row[m]
                         + sg_r[m] * sm_col[m];
            }
            f = acc;
        }
        float q = se[idx] + f;
        if (MODE == 2) {
            out[(long)idx * 2 + 0] = 1.f / (1.f + expf(q));
            out[(long)idx * 2 + 1] = 1.f / (1.f + expf(-q));
        } else {
            float q1v = 1.f / (1.f + expf(-q));
            int ob = (parity ^ 1) & 1;
            g_q1 [ob][idx] = q1v;
            g_q1T[ob][(b * S + h) * S + m] = q1v;
        }
    }
}

extern "C" void kernel_launch(void* const* d_in, const int* in_sizes, int n_in,
                              void* d_out, int out_size)
{
    const float* se = (const float*)d_in[0];
    const float* ss = (const float*)d_in[1];
    const float* sc = (const float*)d_in[2];
    const float* sg = (const float*)d_in[3];
    const int* mask = (const int*)d_in[4];
    float* out = (float*)d_out;

    int BSS = in_sizes[0];                  // B*S*S
    int S = in_sizes[1] / BSS;              // (B*S^3)/(B*S^2)
    int B = BSS / (S * S);

    excl_build_kernel<<<B * S, (S + 31) & ~31>>>(mask, S);

    const int ROWS = 16;
    int ntile = (S + ROWS - 1) / ROWS;
    dim3 grid(B * S * ntile);
    size_t smem = (2 * (size_t)S + 32 + 3 * (size_t)ROWS * S) * sizeof(float);

    mfvi_kernel<0><<<grid, 128, smem>>>(se, ss, sc, sg, mask, out, S, 1);
    mfvi_kernel<1><<<grid, 128, smem>>>(se, ss, sc, sg, mask, out, S, 0);
    mfvi_kernel<2><<<grid, 128, smem>>>(se, ss, sc, sg, mask, out, S, 1);
}